// round 9
// baseline (speedup 1.0000x reference)
#include <cuda_runtime.h>
#include <cuda_fp16.h>
#include <cstdint>
#include <cstddef>

// ---------------------------------------------------------------------------
// FFB encoder (round 8): 2 CTAs/SM for cross-CTA phase overlap.
// mma.sync f16 3-term compensated GEMMs, ldmatrix, cp.async.cg K=16 W slabs.
//   x@W = xh@Whi + xl@Whi + xh@Wlo
// ---------------------------------------------------------------------------

#define TM    32             // points per CTA
#define XH    264            // half stride of activation rows (528B: LDSM conflict-free)
#define WROW  40             // halfs per W slab row: [16 hi | 16 lo | 8 pad] (80B stride)
#define WBUFH 10240          // halfs per slab buffer (256 rows x 40)

// ---- SMEM byte offsets ----
#define SM_XSH  0            // 16896
#define SM_XSL  16896        // 16896
#define SM_WBUF 33792        // 40960 (2 buffers x 20480 B)
#define SM_GSM  74752        // 1536:  [6][32][2] f32 grid feats
#define SM_ASM  76288        // 12288: [6][2][256] f32
#define SM_PSM  88576        // 384:   [32][3]
#define SM_W0M  88960        // 4096:  scaled W0/b0
#define SMEM_TOTAL 93056

// W planes: [l][part(hi=0,lo=1)][n][k] halfs
__device__ __align__(16) __half g_WsT[6 * 2 * 256 * 256];
__device__ __align__(16) __half g_WhT[6 * 2 * 256 * 256];

__device__ __forceinline__ unsigned smem_u32(const void* p) {
    unsigned a;
    asm("{ .reg .u64 t; cvta.to.shared.u64 t, %1; cvt.u32.u64 %0, t; }" : "=r"(a) : "l"(p));
    return a;
}

// range-reduced sin: full __sinf accuracy for |x| up to ~1e3
__device__ __forceinline__ float sinr(float x) {
    float k = rintf(x * 0.15915494309189535f);
    float r = fmaf(k, -6.2831855f, x);
    r = fmaf(k, 1.7484555e-7f, r);
    return __sinf(r);
}

__global__ void prep_kernel(const float* __restrict__ Ws, const float* __restrict__ Wh) {
    int idx = blockIdx.x * 256 + threadIdx.x;
    if (idx < 6 * 256 * 256) {
        int l = idx >> 16, rem = idx & 65535, n = rem >> 8, k = rem & 255;
        int src = (l << 16) + (k << 8) + n;             // transpose [k][n] -> [n][k]
        int dhi = ((l * 2 + 0) * 256 + n) * 256 + k;
        int dlo = ((l * 2 + 1) * 256 + n) * 256 + k;
        float ws = 5.0f * Ws[src];
        float wh = 10.0f * Wh[src];
        __half wsh = __float2half_rn(ws);
        __half whh = __float2half_rn(wh);
        g_WsT[dhi] = wsh; g_WsT[dlo] = __float2half_rn(ws - __half2float(wsh));
        g_WhT[dhi] = whh; g_WhT[dlo] = __float2half_rn(wh - __half2float(whh));
    }
}

__device__ __forceinline__ void mma16816(float* c, const unsigned* a, unsigned b0, unsigned b1) {
    asm volatile(
        "mma.sync.aligned.m16n8k16.row.col.f32.f16.f16.f32 "
        "{%0,%1,%2,%3}, {%4,%5,%6,%7}, {%8,%9}, {%0,%1,%2,%3};\n"
        : "+f"(c[0]), "+f"(c[1]), "+f"(c[2]), "+f"(c[3])
        : "r"(a[0]), "r"(a[1]), "r"(a[2]), "r"(a[3]), "r"(b0), "r"(b1));
}

#define LDSM_X4(r0, r1, r2, r3, addr) \
    asm volatile("ldmatrix.sync.aligned.m8n8.x4.shared.b16 {%0,%1,%2,%3}, [%4];" \
        : "=r"(r0), "=r"(r1), "=r"(r2), "=r"(r3) : "r"(addr))

__device__ __forceinline__ void cpasync16cg(unsigned dst, const void* src) {
    asm volatile("cp.async.cg.shared.global [%0], [%1], 16;\n" :: "r"(dst), "l"(src));
}
template <int NN> __device__ __forceinline__ void cpwait() {
    asm volatile("cp.async.wait_group %0;\n" :: "n"(NN));
}

// fill one K=16 slab (hi+lo interleaved per row) into buffer at smem byte addr bufb
__device__ __forceinline__ void fill_slab(const __half* __restrict__ plane, int s,
                                          unsigned bufb, int tid) {
    #pragma unroll
    for (int it = 0; it < 4; it++) {
        int c = tid + it * 256;              // 0..1023
        int n = c >> 2, j = c & 3;
        int part = j >> 1;                   // 0 = hi, 1 = lo
        int col8 = (j & 1) << 3;             // 0 or 8
        const __half* src = plane + ((size_t)((part << 8) + n)) * 256 + s * 16 + col8;
        unsigned dst = bufb + (unsigned)(n * WROW + part * 16 + col8) * 2;
        cpasync16cg(dst, src);
    }
    asm volatile("cp.async.commit_group;\n");
}

// C[32,256] += x @ W^T with 3-term compensation. 8 warps: 2m x 4n.
__device__ __forceinline__ void do_gemm(float (&c)[8][4],
                                        const __half* __restrict__ plane,
                                        unsigned sbase, unsigned aoffB,
                                        unsigned boffrow, unsigned bcol, int tid) {
    fill_slab(plane, 0, sbase + SM_WBUF, tid);
    #pragma unroll 1
    for (int s = 0; s < 16; s++) {
        if (s < 15) {
            fill_slab(plane, s + 1, sbase + SM_WBUF + (unsigned)(((s + 1) & 1) * WBUFH) * 2, tid);
            cpwait<1>();
        } else {
            cpwait<0>();
        }
        __syncthreads();
        unsigned wb = sbase + SM_WBUF + (unsigned)((s & 1) * WBUFH) * 2;
        unsigned ah[4], al[4];
        LDSM_X4(ah[0], ah[1], ah[2], ah[3], sbase + SM_XSH + aoffB + (unsigned)(s * 16) * 2);
        LDSM_X4(al[0], al[1], al[2], al[3], sbase + SM_XSL + aoffB + (unsigned)(s * 16) * 2);
        unsigned b[8][2];
        // --- hi part of W ---
        #pragma unroll
        for (int ntp = 0; ntp < 4; ntp++) {
            unsigned r0, r1, r2, r3;
            LDSM_X4(r0, r1, r2, r3, wb + (unsigned)((boffrow + ntp * 16) * WROW + bcol) * 2);
            b[2 * ntp][0] = r0; b[2 * ntp][1] = r1;
            b[2 * ntp + 1][0] = r2; b[2 * ntp + 1][1] = r3;
        }
        #pragma unroll
        for (int nt = 0; nt < 8; nt++) {
            mma16816(c[nt], ah, b[nt][0], b[nt][1]);
            mma16816(c[nt], al, b[nt][0], b[nt][1]);
        }
        // --- lo part of W ---
        #pragma unroll
        for (int ntp = 0; ntp < 4; ntp++) {
            unsigned r0, r1, r2, r3;
            LDSM_X4(r0, r1, r2, r3, wb + (unsigned)((boffrow + ntp * 16) * WROW + 16 + bcol) * 2);
            b[2 * ntp][0] = r0; b[2 * ntp][1] = r1;
            b[2 * ntp + 1][0] = r2; b[2 * ntp + 1][1] = r3;
        }
        #pragma unroll
        for (int nt = 0; nt < 8; nt++)
            mma16816(c[nt], ah, b[nt][0], b[nt][1]);
        __syncthreads();
    }
}

__global__ void __launch_bounds__(256, 2) ffb_kernel(
    const float* __restrict__ in_pos, const float* __restrict__ table,
    const float* __restrict__ ffn_A, const float* __restrict__ W0,
    const float* __restrict__ b0v, const float* __restrict__ bsv,
    const float* __restrict__ bhv, float* __restrict__ out) {
    extern __shared__ char smem[];
    const unsigned sbase = smem_u32(smem);
    __half* xsh = (__half*)(smem + SM_XSH);
    __half* xsl = (__half*)(smem + SM_XSL);
    float* gsm = (float*)(smem + SM_GSM);
    float* Asm = (float*)(smem + SM_ASM);
    float* psm = (float*)(smem + SM_PSM);
    float* w0m = (float*)(smem + SM_W0M);

    const int tid = threadIdx.x;
    const int lane = tid & 31, wid = tid >> 5;
    const int g = lane >> 2, tg = lane & 3;
    const int wm = wid >> 2, wn = wid & 3;        // 2m x 4n warps
    const int rm = wm * 16, cn = wn * 64;
    const int row0 = blockIdx.x * TM;

    // ldmatrix address components
    const unsigned aoffB = (unsigned)((rm + (lane & 15)) * XH + ((lane >> 4) << 3)) * 2;
    const unsigned boffrow = (unsigned)(cn + (lane & 7) + ((lane >> 4) << 3));
    const unsigned bcol = (unsigned)(((lane >> 3) & 1) << 3);

    // ---- prologue staging ----
    for (int i = tid; i < TM * 3; i += 256) psm[i] = in_pos[row0 * 3 + i];
    for (int i = tid; i < 6 * 512; i += 256) {
        int l = i >> 9;
        Asm[i] = 6.283185307179586f * (5.0f * (float)(1 << l)) * ffn_A[i];
    }
    {
        w0m[tid] = 5.0f * W0[tid];
        w0m[256 + tid] = 5.0f * W0[256 + tid];
        w0m[512 + tid] = 5.0f * W0[512 + tid];
        w0m[768 + tid] = 5.0f * b0v[tid];
    }
    __syncthreads();

    // ---- multires hash grid (f32 math matches reference) ----
    if (tid < TM * 6) {
        int t = tid;
        int l = t >> 5;
        int p = t & 31;
        float res = 16.0f * (float)(1 << l);
        float px = (psm[p * 3 + 0] + 1.0f) * 0.5f * res;
        float py = (psm[p * 3 + 1] + 1.0f) * 0.5f * res;
        float pz = (psm[p * 3 + 2] + 1.0f) * 0.5f * res;
        float fx = floorf(px), fy = floorf(py), fz = floorf(pz);
        float frx = px - fx, fry = py - fy, frz = pz - fz;
        int ix = (int)fx, iy = (int)fy, iz = (int)fz;
        float g0 = 0.f, g1 = 0.f;
        const float* tb = table + (size_t)l * (524288 * 2);
        #pragma unroll
        for (int cc = 0; cc < 8; cc++) {
            int ox = (cc >> 2) & 1, oy = (cc >> 1) & 1, oz = cc & 1;
            unsigned h = ((unsigned)(ix + ox))
                       ^ ((unsigned)(iy + oy) * 2654435761u)
                       ^ ((unsigned)(iz + oz) * 805459861u);
            h &= 524287u;
            float2 f2 = *(const float2*)(tb + (size_t)h * 2);
            float w = (ox ? frx : 1.0f - frx) * (oy ? fry : 1.0f - fry) * (oz ? frz : 1.0f - frz);
            g0 = fmaf(w, f2.x, g0);
            g1 = fmaf(w, f2.y, g1);
        }
        gsm[t * 2] = g0; gsm[t * 2 + 1] = g1;
    }

    // ---- layer 0: x = sin(5*(pos @ W0 + b0)) -> hi/lo in smem ----
    for (int i = tid; i < TM * 256; i += 256) {
        int p = i >> 8, n = i & 255;
        float x = fmaf(psm[p * 3 + 2], w0m[512 + n],
                  fmaf(psm[p * 3 + 1], w0m[256 + n],
                  fmaf(psm[p * 3], w0m[n], w0m[768 + n])));
        float sv = sinr(x);
        __half h = __float2half_rn(sv);
        xsh[p * XH + n] = h;
        xsl[p * XH + n] = __float2half_rn(sv - __half2float(h));
    }
    __syncthreads();

    float acc[8][4];
    #pragma unroll
    for (int nt = 0; nt < 8; nt++)
        #pragma unroll
        for (int e = 0; e < 4; e++) acc[nt][e] = 0.f;

    for (int lev = 0; lev < 6; lev++) {
        // ---- GEMM1: c = xs @ (5*Ws)^T + 5*bs ----
        float c[8][4];
        #pragma unroll
        for (int nt = 0; nt < 8; nt++) {
            float2 bv = *(const float2*)(bsv + lev * 256 + cn + nt * 8 + 2 * tg);
            float bx = 5.0f * bv.x, by = 5.0f * bv.y;
            c[nt][0] = bx; c[nt][1] = by; c[nt][2] = bx; c[nt][3] = by;
        }
        do_gemm(c, g_WsT + (size_t)lev * 131072, sbase, aoffB, boffrow, bcol, tid);

        // ---- epilogue 1: x = sin(c) + sin(grid proj); write back hi/lo ----
        {
            int r0 = rm + g;
            float2 gA = *(const float2*)(gsm + (lev * TM + r0) * 2);
            float2 gB = *(const float2*)(gsm + (lev * TM + r0 + 8) * 2);
            #pragma unroll
            for (int nt = 0; nt < 8; nt++) {
                int n0 = cn + nt * 8 + 2 * tg;
                float2 a0 = *(const float2*)(Asm + lev * 512 + n0);
                float2 a1 = *(const float2*)(Asm + lev * 512 + 256 + n0);
                float x0 = sinr(c[nt][0]) + sinr(fmaf(gA.y, a1.x, gA.x * a0.x));
                float x1 = sinr(c[nt][1]) + sinr(fmaf(gA.y, a1.y, gA.x * a0.y));
                float x2 = sinr(c[nt][2]) + sinr(fmaf(gB.y, a1.x, gB.x * a0.x));
                float x3 = sinr(c[nt][3]) + sinr(fmaf(gB.y, a1.y, gB.x * a0.y));
                __half h0 = __float2half_rn(x0), h1 = __float2half_rn(x1);
                __half h2 = __float2half_rn(x2), h3 = __float2half_rn(x3);
                *(__half2*)(xsh + r0 * XH + n0)       = __halves2half2(h0, h1);
                *(__half2*)(xsh + (r0 + 8) * XH + n0) = __halves2half2(h2, h3);
                *(__half2*)(xsl + r0 * XH + n0) =
                    __halves2half2(__float2half_rn(x0 - __half2float(h0)),
                                   __float2half_rn(x1 - __half2float(h1)));
                *(__half2*)(xsl + (r0 + 8) * XH + n0) =
                    __halves2half2(__float2half_rn(x2 - __half2float(h2)),
                                   __float2half_rn(x3 - __half2float(h3)));
            }
        }
        __syncthreads();

        // ---- GEMM2: c2 = xs @ (10*Wh)^T + 10*bh; out += sin(c2) ----
        float c2[8][4];
        #pragma unroll
        for (int nt = 0; nt < 8; nt++) {
            float2 bv = *(const float2*)(bhv + lev * 256 + cn + nt * 8 + 2 * tg);
            float bx = 10.0f * bv.x, by = 10.0f * bv.y;
            c2[nt][0] = bx; c2[nt][1] = by; c2[nt][2] = bx; c2[nt][3] = by;
        }
        do_gemm(c2, g_WhT + (size_t)lev * 131072, sbase, aoffB, boffrow, bcol, tid);
        #pragma unroll
        for (int nt = 0; nt < 8; nt++)
            #pragma unroll
            for (int e = 0; e < 4; e++) acc[nt][e] += sinr(c2[nt][e]);
    }

    // ---- store out [N,256] f32 ----
    #pragma unroll
    for (int nt = 0; nt < 8; nt++) {
        int r = row0 + rm + g;
        int n0 = cn + nt * 8 + 2 * tg;
        *(float2*)(out + (size_t)r * 256 + n0) = make_float2(acc[nt][0], acc[nt][1]);
        *(float2*)(out + (size_t)(r + 8) * 256 + n0) = make_float2(acc[nt][2], acc[nt][3]);
    }
}

extern "C" void kernel_launch(void* const* d_in, const int* in_sizes, int n_in,
                              void* d_out, int out_size) {
    (void)in_sizes; (void)n_in; (void)out_size;
    const float* in_pos = (const float*)d_in[0];
    const float* table  = (const float*)d_in[1];
    const float* ffn_A  = (const float*)d_in[2];
    const float* W0     = (const float*)d_in[3];
    const float* b0     = (const float*)d_in[4];
    const float* Ws     = (const float*)d_in[5];
    const float* bs     = (const float*)d_in[6];
    const float* Wh     = (const float*)d_in[7];
    const float* bh     = (const float*)d_in[8];
    float* out = (float*)d_out;

    cudaFuncSetAttribute(ffb_kernel, cudaFuncAttributeMaxDynamicSharedMemorySize, SMEM_TOTAL);

    prep_kernel<<<1536, 256>>>(Ws, Wh);
    ffb_kernel<<<262144 / TM, 256, SMEM_TOTAL>>>(in_pos, table, ffn_A, W0, b0, bs, bh, out);
}

// round 10
// speedup vs baseline: 1.3840x; 1.3840x over previous
#include <cuda_runtime.h>
#include <cuda_fp16.h>
#include <cstdint>
#include <cstddef>

// ---------------------------------------------------------------------------
// FFB encoder (round 9): round-6 config (TM=64, 512 thr, K=32 slabs) with a
// 3-stage W ring buffer and ONE __syncthreads per k-slab (fill-after-compute).
//   x@W = xh@Whi + xl@Whi + xh@Wlo   (3-term compensated f16 mma.sync)
// ---------------------------------------------------------------------------

#define TM    64             // points per CTA
#define XH    264            // half stride of activation rows (528B: LDSM conflict-free)
#define WROW  40             // halfs per W slab row (80B: LDSM conflict-free)
#define WPART 10240          // halfs per part in one slab buffer (256*40)
#define WBUFH 20480          // halfs per slab buffer (2 parts)
#define WBUFB 40960          // bytes per slab buffer

// ---- SMEM byte offsets ----
#define SM_XSH  0            // 33792
#define SM_XSL  33792        // 33792
#define SM_WBUF 67584        // 122880 (3 buffers x 40960 B)
#define SM_GSM  190464       // 3072:  [6][64][2] f32 grid feats
#define SM_ASM  193536       // 12288: [6][2][256] f32
#define SM_BSM  205824       // 6144:  5*bs
#define SM_BHM  211968       // 6144:  10*bh
#define SM_PSM  218112       // 768:   [64][3]
#define SM_W0M  218880       // 4096:  scaled W0/b0
#define SMEM_TOTAL 222976

// W planes: [l][part(hi=0,lo=1)][n][k] halfs
__device__ __align__(16) __half g_WsT[6 * 2 * 256 * 256];
__device__ __align__(16) __half g_WhT[6 * 2 * 256 * 256];

__device__ __forceinline__ unsigned smem_u32(const void* p) {
    unsigned a;
    asm("{ .reg .u64 t; cvta.to.shared.u64 t, %1; cvt.u32.u64 %0, t; }" : "=r"(a) : "l"(p));
    return a;
}

// range-reduced sin: full __sinf accuracy for |x| up to ~1e3
__device__ __forceinline__ float sinr(float x) {
    float k = rintf(x * 0.15915494309189535f);
    float r = fmaf(k, -6.2831855f, x);
    r = fmaf(k, 1.7484555e-7f, r);
    return __sinf(r);
}

__global__ void prep_kernel(const float* __restrict__ Ws, const float* __restrict__ Wh) {
    int idx = blockIdx.x * 256 + threadIdx.x;
    if (idx < 6 * 256 * 256) {
        int l = idx >> 16, rem = idx & 65535, n = rem >> 8, k = rem & 255;
        int src = (l << 16) + (k << 8) + n;             // transpose [k][n] -> [n][k]
        int dhi = ((l * 2 + 0) * 256 + n) * 256 + k;
        int dlo = ((l * 2 + 1) * 256 + n) * 256 + k;
        float ws = 5.0f * Ws[src];
        float wh = 10.0f * Wh[src];
        __half wsh = __float2half_rn(ws);
        __half whh = __float2half_rn(wh);
        g_WsT[dhi] = wsh; g_WsT[dlo] = __float2half_rn(ws - __half2float(wsh));
        g_WhT[dhi] = whh; g_WhT[dlo] = __float2half_rn(wh - __half2float(whh));
    }
}

__device__ __forceinline__ void mma16816(float* c, const unsigned* a, unsigned b0, unsigned b1) {
    asm volatile(
        "mma.sync.aligned.m16n8k16.row.col.f32.f16.f16.f32 "
        "{%0,%1,%2,%3}, {%4,%5,%6,%7}, {%8,%9}, {%0,%1,%2,%3};\n"
        : "+f"(c[0]), "+f"(c[1]), "+f"(c[2]), "+f"(c[3])
        : "r"(a[0]), "r"(a[1]), "r"(a[2]), "r"(a[3]), "r"(b0), "r"(b1));
}

#define LDSM_X4(r0, r1, r2, r3, addr) \
    asm volatile("ldmatrix.sync.aligned.m8n8.x4.shared.b16 {%0,%1,%2,%3}, [%4];" \
        : "=r"(r0), "=r"(r1), "=r"(r2), "=r"(r3) : "r"(addr))

__device__ __forceinline__ void cpasync16cg(unsigned dst, const void* src) {
    asm volatile("cp.async.cg.shared.global [%0], [%1], 16;\n" :: "r"(dst), "l"(src));
}
template <int NN> __device__ __forceinline__ void cpwait() {
    asm volatile("cp.async.wait_group %0;\n" :: "n"(NN));
}

// fill one K=32 slab (both hi/lo parts) into buffer at smem byte addr bufb
__device__ __forceinline__ void fill_slab(const __half* __restrict__ plane, int s,
                                          unsigned bufb, int tid) {
    #pragma unroll
    for (int it = 0; it < 4; it++) {
        int c = tid + it * 512;              // 0..2047
        int part = c >> 10, n = (c >> 2) & 255, j = c & 3;
        const __half* src = plane + ((size_t)((part << 8) + n)) * 256 + s * 32 + j * 8;
        unsigned dst = bufb + (unsigned)(part * WPART + n * WROW + j * 8) * 2;
        cpasync16cg(dst, src);
    }
    asm volatile("cp.async.commit_group;\n");
}

// C[64,256] += x @ W^T with 3-term compensation. 16 warps: 4m x 4n.
// 3-stage ring, one __syncthreads per k-slab (fill issued AFTER compute; the
// next phase's barrier orders it against all threads' previous compute).
__device__ __forceinline__ void do_gemm(float (&c)[8][4],
                                        const __half* __restrict__ plane,
                                        unsigned sbase, unsigned aoffB,
                                        unsigned boffrow, unsigned bcol, int tid) {
    fill_slab(plane, 0, sbase + SM_WBUF, tid);
    fill_slab(plane, 1, sbase + SM_WBUF + WBUFB, tid);
    #pragma unroll 1
    for (int s = 0; s < 8; s++) {
        if (s < 7) cpwait<1>(); else cpwait<0>();   // slab s resident
        __syncthreads();                            // visible to all; orders ring reuse
        unsigned wb = sbase + SM_WBUF + (unsigned)((s % 3) * WBUFB);
        #pragma unroll
        for (int t = 0; t < 2; t++) {
            int kabs = s * 32 + t * 16;
            unsigned ah[4], al[4];
            LDSM_X4(ah[0], ah[1], ah[2], ah[3], sbase + SM_XSH + aoffB + (unsigned)kabs * 2);
            LDSM_X4(al[0], al[1], al[2], al[3], sbase + SM_XSL + aoffB + (unsigned)kabs * 2);
            unsigned b[8][2];
            // --- hi part of W ---
            #pragma unroll
            for (int ntp = 0; ntp < 4; ntp++) {
                unsigned r0, r1, r2, r3;
                LDSM_X4(r0, r1, r2, r3,
                        wb + (unsigned)((boffrow + ntp * 16) * WROW + bcol + t * 16) * 2);
                b[2 * ntp][0] = r0; b[2 * ntp][1] = r1;
                b[2 * ntp + 1][0] = r2; b[2 * ntp + 1][1] = r3;
            }
            #pragma unroll
            for (int nt = 0; nt < 8; nt++) {
                mma16816(c[nt], ah, b[nt][0], b[nt][1]);
                mma16816(c[nt], al, b[nt][0], b[nt][1]);
            }
            // --- lo part of W ---
            #pragma unroll
            for (int ntp = 0; ntp < 4; ntp++) {
                unsigned r0, r1, r2, r3;
                LDSM_X4(r0, r1, r2, r3,
                        wb + (unsigned)(WPART + (boffrow + ntp * 16) * WROW + bcol + t * 16) * 2);
                b[2 * ntp][0] = r0; b[2 * ntp][1] = r1;
                b[2 * ntp + 1][0] = r2; b[2 * ntp + 1][1] = r3;
            }
            #pragma unroll
            for (int nt = 0; nt < 8; nt++)
                mma16816(c[nt], ah, b[nt][0], b[nt][1]);
        }
        if (s < 6)
            fill_slab(plane, s + 2, sbase + SM_WBUF + (unsigned)(((s + 2) % 3) * WBUFB), tid);
    }
    __syncthreads();   // protect ring before next do_gemm / epilogue smem writes
}

__global__ void __launch_bounds__(512, 1) ffb_kernel(
    const float* __restrict__ in_pos, const float* __restrict__ table,
    const float* __restrict__ ffn_A, const float* __restrict__ W0,
    const float* __restrict__ b0v, const float* __restrict__ bsv,
    const float* __restrict__ bhv, float* __restrict__ out) {
    extern __shared__ char smem[];
    const unsigned sbase = smem_u32(smem);
    __half* xsh = (__half*)(smem + SM_XSH);
    __half* xsl = (__half*)(smem + SM_XSL);
    float* gsm = (float*)(smem + SM_GSM);
    float* Asm = (float*)(smem + SM_ASM);
    float* bsm = (float*)(smem + SM_BSM);
    float* bhm = (float*)(smem + SM_BHM);
    float* psm = (float*)(smem + SM_PSM);
    float* w0m = (float*)(smem + SM_W0M);

    const int tid = threadIdx.x;
    const int lane = tid & 31, wid = tid >> 5;
    const int g = lane >> 2, tg = lane & 3;
    const int wm = wid >> 2, wn = wid & 3;        // 4m x 4n warps
    const int rm = wm * 16, cn = wn * 64;
    const int row0 = blockIdx.x * TM;

    // ldmatrix address components (byte offsets)
    const unsigned aoffB = (unsigned)((rm + (lane & 15)) * XH + ((lane >> 4) << 3)) * 2;
    const unsigned boffrow = (unsigned)(cn + (lane & 7) + ((lane >> 4) << 3));
    const unsigned bcol = (unsigned)(((lane >> 3) & 1) << 3);

    // ---- prologue staging ----
    for (int i = tid; i < TM * 3; i += 512) psm[i] = in_pos[row0 * 3 + i];
    for (int i = tid; i < 6 * 256; i += 512) {
        bsm[i] = 5.0f * bsv[i];
        bhm[i] = 10.0f * bhv[i];
    }
    for (int i = tid; i < 6 * 512; i += 512) {
        int l = i >> 9;
        Asm[i] = 6.283185307179586f * (5.0f * (float)(1 << l)) * ffn_A[i];
    }
    if (tid < 256) {
        w0m[tid] = 5.0f * W0[tid];
        w0m[256 + tid] = 5.0f * W0[256 + tid];
        w0m[512 + tid] = 5.0f * W0[512 + tid];
        w0m[768 + tid] = 5.0f * b0v[tid];
    }
    __syncthreads();

    // ---- multires hash grid (f32 math matches reference) ----
    if (tid < TM * 6) {
        int t = tid;
        int l = t >> 6;
        int p = t & 63;
        float res = 16.0f * (float)(1 << l);
        float px = (psm[p * 3 + 0] + 1.0f) * 0.5f * res;
        float py = (psm[p * 3 + 1] + 1.0f) * 0.5f * res;
        float pz = (psm[p * 3 + 2] + 1.0f) * 0.5f * res;
        float fx = floorf(px), fy = floorf(py), fz = floorf(pz);
        float frx = px - fx, fry = py - fy, frz = pz - fz;
        int ix = (int)fx, iy = (int)fy, iz = (int)fz;
        float g0 = 0.f, g1 = 0.f;
        const float* tb = table + (size_t)l * (524288 * 2);
        #pragma unroll
        for (int cc = 0; cc < 8; cc++) {
            int ox = (cc >> 2) & 1, oy = (cc >> 1) & 1, oz = cc & 1;
            unsigned h = ((unsigned)(ix + ox))
                       ^ ((unsigned)(iy + oy) * 2654435761u)
                       ^ ((unsigned)(iz + oz) * 805459861u);
            h &= 524287u;
            float2 f2 = *(const float2*)(tb + (size_t)h * 2);
            float w = (ox ? frx : 1.0f - frx) * (oy ? fry : 1.0f - fry) * (oz ? frz : 1.0f - frz);
            g0 = fmaf(w, f2.x, g0);
            g1 = fmaf(w, f2.y, g1);
        }
        gsm[t * 2] = g0; gsm[t * 2 + 1] = g1;
    }

    // ---- layer 0: x = sin(5*(pos @ W0 + b0)) -> hi/lo in smem ----
    for (int i = tid; i < TM * 256; i += 512) {
        int p = i >> 8, n = i & 255;
        float x = fmaf(psm[p * 3 + 2], w0m[512 + n],
                  fmaf(psm[p * 3 + 1], w0m[256 + n],
                  fmaf(psm[p * 3], w0m[n], w0m[768 + n])));
        float sv = sinr(x);
        __half h = __float2half_rn(sv);
        xsh[p * XH + n] = h;
        xsl[p * XH + n] = __float2half_rn(sv - __half2float(h));
    }
    __syncthreads();

    float acc[8][4];
    #pragma unroll
    for (int nt = 0; nt < 8; nt++)
        #pragma unroll
        for (int e = 0; e < 4; e++) acc[nt][e] = 0.f;

    for (int lev = 0; lev < 6; lev++) {
        // ---- GEMM1: c = xs @ (5*Ws)^T + 5*bs ----
        float c[8][4];
        #pragma unroll
        for (int nt = 0; nt < 8; nt++) {
            float2 bv = *(const float2*)(bsm + lev * 256 + cn + nt * 8 + 2 * tg);
            c[nt][0] = bv.x; c[nt][1] = bv.y; c[nt][2] = bv.x; c[nt][3] = bv.y;
        }
        do_gemm(c, g_WsT + (size_t)lev * 131072, sbase, aoffB, boffrow, bcol, tid);

        // ---- epilogue 1: x = sin(c) + sin(grid proj); write back hi/lo ----
        {
            int r0 = rm + g;
            float2 gA = *(const float2*)(gsm + (lev * 64 + r0) * 2);
            float2 gB = *(const float2*)(gsm + (lev * 64 + r0 + 8) * 2);
            #pragma unroll
            for (int nt = 0; nt < 8; nt++) {
                int n0 = cn + nt * 8 + 2 * tg;
                float2 a0 = *(const float2*)(Asm + lev * 512 + n0);
                float2 a1 = *(const float2*)(Asm + lev * 512 + 256 + n0);
                float x0 = sinr(c[nt][0]) + sinr(fmaf(gA.y, a1.x, gA.x * a0.x));
                float x1 = sinr(c[nt][1]) + sinr(fmaf(gA.y, a1.y, gA.x * a0.y));
                float x2 = sinr(c[nt][2]) + sinr(fmaf(gB.y, a1.x, gB.x * a0.x));
                float x3 = sinr(c[nt][3]) + sinr(fmaf(gB.y, a1.y, gB.x * a0.y));
                __half h0 = __float2half_rn(x0), h1 = __float2half_rn(x1);
                __half h2 = __float2half_rn(x2), h3 = __float2half_rn(x3);
                *(__half2*)(xsh + r0 * XH + n0)       = __halves2half2(h0, h1);
                *(__half2*)(xsh + (r0 + 8) * XH + n0) = __halves2half2(h2, h3);
                *(__half2*)(xsl + r0 * XH + n0) =
                    __halves2half2(__float2half_rn(x0 - __half2float(h0)),
                                   __float2half_rn(x1 - __half2float(h1)));
                *(__half2*)(xsl + (r0 + 8) * XH + n0) =
                    __halves2half2(__float2half_rn(x2 - __half2float(h2)),
                                   __float2half_rn(x3 - __half2float(h3)));
            }
        }
        __syncthreads();

        // ---- GEMM2: c2 = xs @ (10*Wh)^T + 10*bh; out += sin(c2) ----
        float c2[8][4];
        #pragma unroll
        for (int nt = 0; nt < 8; nt++) {
            float2 bv = *(const float2*)(bhm + lev * 256 + cn + nt * 8 + 2 * tg);
            c2[nt][0] = bv.x; c2[nt][1] = bv.y; c2[nt][2] = bv.x; c2[nt][3] = bv.y;
        }
        do_gemm(c2, g_WhT + (size_t)lev * 131072, sbase, aoffB, boffrow, bcol, tid);
        #pragma unroll
        for (int nt = 0; nt < 8; nt++)
            #pragma unroll
            for (int e = 0; e < 4; e++) acc[nt][e] += sinr(c2[nt][e]);
        // trailing __syncthreads inside do_gemm protects the W ring; epilogue-2
        // is register-only so the next GEMM1 may start filling immediately.
    }

    // ---- store out [N,256] f32 ----
    #pragma unroll
    for (int nt = 0; nt < 8; nt++) {
        int r = row0 + rm + g;
        int n0 = cn + nt * 8 + 2 * tg;
        *(float2*)(out + (size_t)r * 256 + n0) = make_float2(acc[nt][0], acc[nt][1]);
        *(float2*)(out + (size_t)(r + 8) * 256 + n0) = make_float2(acc[nt][2], acc[nt][3]);
    }
}

extern "C" void kernel_launch(void* const* d_in, const int* in_sizes, int n_in,
                              void* d_out, int out_size) {
    (void)in_sizes; (void)n_in; (void)out_size;
    const float* in_pos = (const float*)d_in[0];
    const float* table  = (const float*)d_in[1];
    const float* ffn_A  = (const float*)d_in[2];
    const float* W0     = (const float*)d_in[3];
    const float* b0     = (const float*)d_in[4];
    const float* Ws     = (const float*)d_in[5];
    const float* bs     = (const float*)d_in[6];
    const float* Wh     = (const float*)d_in[7];
    const float* bh     = (const float*)d_in[8];
    float* out = (float*)d_out;

    cudaFuncSetAttribute(ffb_kernel, cudaFuncAttributeMaxDynamicSharedMemorySize, SMEM_TOTAL);

    prep_kernel<<<1536, 256>>>(Ws, Wh);
    ffb_kernel<<<262144 / TM, 512, SMEM_TOTAL>>>(in_pos, table, ffn_A, W0, b0, bs, bh, out);
}

// round 11
// speedup vs baseline: 1.4896x; 1.0763x over previous
#include <cuda_runtime.h>
#include <cuda_fp16.h>
#include <cstdint>
#include <cstddef>

// ---------------------------------------------------------------------------
// FFB encoder (round 10): 2m x 8n warp layout (m32n32/warp) to halve B LDSM
// duplication + cross-phase slab prefetch. 3-term compensated f16 mma.sync.
//   x@W = xh@Whi + xl@Whi + xh@Wlo
// ---------------------------------------------------------------------------

#define TM    64             // points per CTA
#define XH    264            // half stride of activation rows (528B: LDSM conflict-free)
#define WROW  40             // halfs per W slab row (80B: LDSM conflict-free)
#define WPART 10240          // halfs per part in one slab buffer (256*40)
#define WBUFH 20480          // halfs per slab buffer (2 parts)
#define WBUFB 40960          // bytes per slab buffer

// ---- SMEM byte offsets ----
#define SM_XSH  0            // 33792
#define SM_XSL  33792        // 33792
#define SM_WBUF 67584        // 122880 (3 buffers x 40960 B)
#define SM_GSM  190464       // 3072:  [6][64][2] f32 grid feats
#define SM_ASM  193536       // 12288: [6][2][256] f32
#define SM_BSM  205824       // 6144:  5*bs
#define SM_BHM  211968       // 6144:  10*bh
#define SM_PSM  218112       // 768:   [64][3]
#define SM_W0M  218880       // 4096:  scaled W0/b0
#define SMEM_TOTAL 222976

// W planes: [l][part(hi=0,lo=1)][n][k] halfs
__device__ __align__(16) __half g_WsT[6 * 2 * 256 * 256];
__device__ __align__(16) __half g_WhT[6 * 2 * 256 * 256];

__device__ __forceinline__ unsigned smem_u32(const void* p) {
    unsigned a;
    asm("{ .reg .u64 t; cvta.to.shared.u64 t, %1; cvt.u32.u64 %0, t; }" : "=r"(a) : "l"(p));
    return a;
}

// range-reduced sin: full __sinf accuracy for |x| up to ~1e3
__device__ __forceinline__ float sinr(float x) {
    float k = rintf(x * 0.15915494309189535f);
    float r = fmaf(k, -6.2831855f, x);
    r = fmaf(k, 1.7484555e-7f, r);
    return __sinf(r);
}

__global__ void prep_kernel(const float* __restrict__ Ws, const float* __restrict__ Wh) {
    int idx = blockIdx.x * 256 + threadIdx.x;
    if (idx < 6 * 256 * 256) {
        int l = idx >> 16, rem = idx & 65535, n = rem >> 8, k = rem & 255;
        int src = (l << 16) + (k << 8) + n;             // transpose [k][n] -> [n][k]
        int dhi = ((l * 2 + 0) * 256 + n) * 256 + k;
        int dlo = ((l * 2 + 1) * 256 + n) * 256 + k;
        float ws = 5.0f * Ws[src];
        float wh = 10.0f * Wh[src];
        __half wsh = __float2half_rn(ws);
        __half whh = __float2half_rn(wh);
        g_WsT[dhi] = wsh; g_WsT[dlo] = __float2half_rn(ws - __half2float(wsh));
        g_WhT[dhi] = whh; g_WhT[dlo] = __float2half_rn(wh - __half2float(whh));
    }
}

__device__ __forceinline__ void mma16816(float* c, const unsigned* a, unsigned b0, unsigned b1) {
    asm volatile(
        "mma.sync.aligned.m16n8k16.row.col.f32.f16.f16.f32 "
        "{%0,%1,%2,%3}, {%4,%5,%6,%7}, {%8,%9}, {%0,%1,%2,%3};\n"
        : "+f"(c[0]), "+f"(c[1]), "+f"(c[2]), "+f"(c[3])
        : "r"(a[0]), "r"(a[1]), "r"(a[2]), "r"(a[3]), "r"(b0), "r"(b1));
}

#define LDSM_X4(r0, r1, r2, r3, addr) \
    asm volatile("ldmatrix.sync.aligned.m8n8.x4.shared.b16 {%0,%1,%2,%3}, [%4];" \
        : "=r"(r0), "=r"(r1), "=r"(r2), "=r"(r3) : "r"(addr))

__device__ __forceinline__ void cpasync16cg(unsigned dst, const void* src) {
    asm volatile("cp.async.cg.shared.global [%0], [%1], 16;\n" :: "r"(dst), "l"(src));
}
template <int NN> __device__ __forceinline__ void cpwait() {
    asm volatile("cp.async.wait_group %0;\n" :: "n"(NN));
}

// fill one K=32 slab (both hi/lo parts) into buffer at smem byte addr bufb
__device__ __forceinline__ void fill_slab(const __half* __restrict__ plane, int s,
                                          unsigned bufb, int tid) {
    #pragma unroll
    for (int it = 0; it < 4; it++) {
        int c = tid + it * 512;              // 0..2047
        int part = c >> 10, n = (c >> 2) & 255, j = c & 3;
        const __half* src = plane + ((size_t)((part << 8) + n)) * 256 + s * 32 + j * 8;
        unsigned dst = bufb + (unsigned)(part * WPART + n * WROW + j * 8) * 2;
        cpasync16cg(dst, src);
    }
    asm volatile("cp.async.commit_group;\n");
}

// C[64,256] += x @ W^T with 3-term compensation. 16 warps: 2m x 8n (m32 n32).
// Caller must have issued fills for slabs 0 and 1 of `plane` already.
// 3-stage ring, one __syncthreads per k-slab.
__device__ __forceinline__ void do_gemm(float (&c)[2][4][4],
                                        const __half* __restrict__ plane,
                                        unsigned sbase, unsigned aoff0, unsigned aoff1,
                                        unsigned boffrow, unsigned bcol, int tid) {
    #pragma unroll 1
    for (int s = 0; s < 8; s++) {
        if (s < 7) cpwait<1>(); else cpwait<0>();   // slab s resident
        __syncthreads();                            // visible to all; orders ring reuse
        unsigned wb = sbase + SM_WBUF + (unsigned)((s % 3) * WBUFB);
        #pragma unroll
        for (int t = 0; t < 2; t++) {
            unsigned koff = (unsigned)((s * 32 + t * 16) * 2);
            unsigned ah[2][4], al[2][4];
            LDSM_X4(ah[0][0], ah[0][1], ah[0][2], ah[0][3], sbase + SM_XSH + aoff0 + koff);
            LDSM_X4(ah[1][0], ah[1][1], ah[1][2], ah[1][3], sbase + SM_XSH + aoff1 + koff);
            LDSM_X4(al[0][0], al[0][1], al[0][2], al[0][3], sbase + SM_XSL + aoff0 + koff);
            LDSM_X4(al[1][0], al[1][1], al[1][2], al[1][3], sbase + SM_XSL + aoff1 + koff);
            unsigned b[4][2];
            // --- hi part of W ---
            #pragma unroll
            for (int ntp = 0; ntp < 2; ntp++) {
                unsigned r0, r1, r2, r3;
                LDSM_X4(r0, r1, r2, r3,
                        wb + (unsigned)((boffrow + ntp * 16) * WROW + bcol + t * 16) * 2);
                b[2 * ntp][0] = r0; b[2 * ntp][1] = r1;
                b[2 * ntp + 1][0] = r2; b[2 * ntp + 1][1] = r3;
            }
            #pragma unroll
            for (int mt = 0; mt < 2; mt++)
                #pragma unroll
                for (int nt = 0; nt < 4; nt++) {
                    mma16816(c[mt][nt], ah[mt], b[nt][0], b[nt][1]);
                    mma16816(c[mt][nt], al[mt], b[nt][0], b[nt][1]);
                }
            // --- lo part of W ---
            #pragma unroll
            for (int ntp = 0; ntp < 2; ntp++) {
                unsigned r0, r1, r2, r3;
                LDSM_X4(r0, r1, r2, r3,
                        wb + (unsigned)(WPART + (boffrow + ntp * 16) * WROW + bcol + t * 16) * 2);
                b[2 * ntp][0] = r0; b[2 * ntp][1] = r1;
                b[2 * ntp + 1][0] = r2; b[2 * ntp + 1][1] = r3;
            }
            #pragma unroll
            for (int mt = 0; mt < 2; mt++)
                #pragma unroll
                for (int nt = 0; nt < 4; nt++)
                    mma16816(c[mt][nt], ah[mt], b[nt][0], b[nt][1]);
        }
        if (s < 6)
            fill_slab(plane, s + 2, sbase + SM_WBUF + (unsigned)(((s + 2) % 3) * WBUFB), tid);
    }
    __syncthreads();   // ring protected: caller may now prefetch next plane's slabs 0/1
}

__global__ void __launch_bounds__(512, 1) ffb_kernel(
    const float* __restrict__ in_pos, const float* __restrict__ table,
    const float* __restrict__ ffn_A, const float* __restrict__ W0,
    const float* __restrict__ b0v, const float* __restrict__ bsv,
    const float* __restrict__ bhv, float* __restrict__ out) {
    extern __shared__ char smem[];
    const unsigned sbase = smem_u32(smem);
    __half* xsh = (__half*)(smem + SM_XSH);
    __half* xsl = (__half*)(smem + SM_XSL);
    float* gsm = (float*)(smem + SM_GSM);
    float* Asm = (float*)(smem + SM_ASM);
    float* bsm = (float*)(smem + SM_BSM);
    float* bhm = (float*)(smem + SM_BHM);
    float* psm = (float*)(smem + SM_PSM);
    float* w0m = (float*)(smem + SM_W0M);

    const int tid = threadIdx.x;
    const int lane = tid & 31, wid = tid >> 5;
    const int g = lane >> 2, tg = lane & 3;
    const int wm = wid >> 3, wn = wid & 7;        // 2m x 8n warps
    const int rm = wm * 32, cn = wn * 32;
    const int row0 = blockIdx.x * TM;

    // ldmatrix address components (byte offsets)
    const unsigned aoff0 = (unsigned)((rm + (lane & 15)) * XH + ((lane >> 4) << 3)) * 2;
    const unsigned aoff1 = aoff0 + (unsigned)(16 * XH) * 2;
    const unsigned boffrow = (unsigned)(cn + (lane & 7) + ((lane >> 4) << 3));
    const unsigned bcol = (unsigned)(((lane >> 3) & 1) << 3);

    // ---- prologue staging ----
    for (int i = tid; i < TM * 3; i += 512) psm[i] = in_pos[row0 * 3 + i];
    for (int i = tid; i < 6 * 256; i += 512) {
        bsm[i] = 5.0f * bsv[i];
        bhm[i] = 10.0f * bhv[i];
    }
    for (int i = tid; i < 6 * 512; i += 512) {
        int l = i >> 9;
        Asm[i] = 6.283185307179586f * (5.0f * (float)(1 << l)) * ffn_A[i];
    }
    if (tid < 256) {
        w0m[tid] = 5.0f * W0[tid];
        w0m[256 + tid] = 5.0f * W0[256 + tid];
        w0m[512 + tid] = 5.0f * W0[512 + tid];
        w0m[768 + tid] = 5.0f * b0v[tid];
    }
    __syncthreads();

    // prefetch level-0 GEMM1 slabs 0/1 — overlaps hash grid + layer 0
    fill_slab(g_WsT, 0, sbase + SM_WBUF, tid);
    fill_slab(g_WsT, 1, sbase + SM_WBUF + WBUFB, tid);

    // ---- multires hash grid (f32 math matches reference) ----
    if (tid < TM * 6) {
        int t = tid;
        int l = t >> 6;
        int p = t & 63;
        float res = 16.0f * (float)(1 << l);
        float px = (psm[p * 3 + 0] + 1.0f) * 0.5f * res;
        float py = (psm[p * 3 + 1] + 1.0f) * 0.5f * res;
        float pz = (psm[p * 3 + 2] + 1.0f) * 0.5f * res;
        float fx = floorf(px), fy = floorf(py), fz = floorf(pz);
        float frx = px - fx, fry = py - fy, frz = pz - fz;
        int ix = (int)fx, iy = (int)fy, iz = (int)fz;
        float g0 = 0.f, g1 = 0.f;
        const float* tb = table + (size_t)l * (524288 * 2);
        #pragma unroll
        for (int cc = 0; cc < 8; cc++) {
            int ox = (cc >> 2) & 1, oy = (cc >> 1) & 1, oz = cc & 1;
            unsigned h = ((unsigned)(ix + ox))
                       ^ ((unsigned)(iy + oy) * 2654435761u)
                       ^ ((unsigned)(iz + oz) * 805459861u);
            h &= 524287u;
            float2 f2 = *(const float2*)(tb + (size_t)h * 2);
            float w = (ox ? frx : 1.0f - frx) * (oy ? fry : 1.0f - fry) * (oz ? frz : 1.0f - frz);
            g0 = fmaf(w, f2.x, g0);
            g1 = fmaf(w, f2.y, g1);
        }
        gsm[t * 2] = g0; gsm[t * 2 + 1] = g1;
    }

    // ---- layer 0: x = sin(5*(pos @ W0 + b0)) -> hi/lo in smem ----
    for (int i = tid; i < TM * 256; i += 512) {
        int p = i >> 8, n = i & 255;
        float x = fmaf(psm[p * 3 + 2], w0m[512 + n],
                  fmaf(psm[p * 3 + 1], w0m[256 + n],
                  fmaf(psm[p * 3], w0m[n], w0m[768 + n])));
        float sv = sinr(x);
        __half h = __float2half_rn(sv);
        xsh[p * XH + n] = h;
        xsl[p * XH + n] = __float2half_rn(sv - __half2float(h));
    }
    __syncthreads();

    float acc[2][4][4];
    #pragma unroll
    for (int mt = 0; mt < 2; mt++)
        #pragma unroll
        for (int nt = 0; nt < 4; nt++)
            #pragma unroll
            for (int e = 0; e < 4; e++) acc[mt][nt][e] = 0.f;

    for (int lev = 0; lev < 6; lev++) {
        const __half* planeS = g_WsT + (size_t)lev * 131072;
        const __half* planeH = g_WhT + (size_t)lev * 131072;

        // ---- GEMM1: c = xs @ (5*Ws)^T + 5*bs ----
        float c[2][4][4];
        #pragma unroll
        for (int nt = 0; nt < 4; nt++) {
            float2 bv = *(const float2*)(bsm + lev * 256 + cn + nt * 8 + 2 * tg);
            #pragma unroll
            for (int mt = 0; mt < 2; mt++) {
                c[mt][nt][0] = bv.x; c[mt][nt][1] = bv.y;
                c[mt][nt][2] = bv.x; c[mt][nt][3] = bv.y;
            }
        }
        do_gemm(c, planeS, sbase, aoff0, aoff1, boffrow, bcol, tid);

        // prefetch GEMM2 slabs 0/1 — overlaps epilogue 1
        fill_slab(planeH, 0, sbase + SM_WBUF, tid);
        fill_slab(planeH, 1, sbase + SM_WBUF + WBUFB, tid);

        // ---- epilogue 1: x = sin(c) + sin(grid proj); write back hi/lo ----
        #pragma unroll
        for (int mt = 0; mt < 2; mt++) {
            int r0 = rm + mt * 16 + g;
            float2 gA = *(const float2*)(gsm + (lev * 64 + r0) * 2);
            float2 gB = *(const float2*)(gsm + (lev * 64 + r0 + 8) * 2);
            #pragma unroll
            for (int nt = 0; nt < 4; nt++) {
                int n0 = cn + nt * 8 + 2 * tg;
                float2 a0 = *(const float2*)(Asm + lev * 512 + n0);
                float2 a1 = *(const float2*)(Asm + lev * 512 + 256 + n0);
                float x0 = sinr(c[mt][nt][0]) + sinr(fmaf(gA.y, a1.x, gA.x * a0.x));
                float x1 = sinr(c[mt][nt][1]) + sinr(fmaf(gA.y, a1.y, gA.x * a0.y));
                float x2 = sinr(c[mt][nt][2]) + sinr(fmaf(gB.y, a1.x, gB.x * a0.x));
                float x3 = sinr(c[mt][nt][3]) + sinr(fmaf(gB.y, a1.y, gB.x * a0.y));
                __half h0 = __float2half_rn(x0), h1 = __float2half_rn(x1);
                __half h2 = __float2half_rn(x2), h3 = __float2half_rn(x3);
                *(__half2*)(xsh + r0 * XH + n0)       = __halves2half2(h0, h1);
                *(__half2*)(xsh + (r0 + 8) * XH + n0) = __halves2half2(h2, h3);
                *(__half2*)(xsl + r0 * XH + n0) =
                    __halves2half2(__float2half_rn(x0 - __half2float(h0)),
                                   __float2half_rn(x1 - __half2float(h1)));
                *(__half2*)(xsl + (r0 + 8) * XH + n0) =
                    __halves2half2(__float2half_rn(x2 - __half2float(h2)),
                                   __float2half_rn(x3 - __half2float(h3)));
            }
        }
        __syncthreads();

        // ---- GEMM2: c2 = xs @ (10*Wh)^T + 10*bh; out += sin(c2) ----
        float c2[2][4][4];
        #pragma unroll
        for (int nt = 0; nt < 4; nt++) {
            float2 bv = *(const float2*)(bhm + lev * 256 + cn + nt * 8 + 2 * tg);
            #pragma unroll
            for (int mt = 0; mt < 2; mt++) {
                c2[mt][nt][0] = bv.x; c2[mt][nt][1] = bv.y;
                c2[mt][nt][2] = bv.x; c2[mt][nt][3] = bv.y;
            }
        }
        do_gemm(c2, planeH, sbase, aoff0, aoff1, boffrow, bcol, tid);

        // prefetch next level's GEMM1 slabs 0/1 — overlaps epilogue 2
        if (lev < 5) {
            fill_slab(g_WsT + (size_t)(lev + 1) * 131072, 0, sbase + SM_WBUF, tid);
            fill_slab(g_WsT + (size_t)(lev + 1) * 131072, 1, sbase + SM_WBUF + WBUFB, tid);
        }

        // ---- epilogue 2: register-only accumulate ----
        #pragma unroll
        for (int mt = 0; mt < 2; mt++)
            #pragma unroll
            for (int nt = 0; nt < 4; nt++)
                #pragma unroll
                for (int e = 0; e < 4; e++)
                    acc[mt][nt][e] += sinr(c2[mt][nt][e]);
    }

    // ---- store out [N,256] f32 ----
    #pragma unroll
    for (int mt = 0; mt < 2; mt++)
        #pragma unroll
        for (int nt = 0; nt < 4; nt++) {
            int r = row0 + rm + mt * 16 + g;
            int n0 = cn + nt * 8 + 2 * tg;
            *(float2*)(out + (size_t)r * 256 + n0) = make_float2(acc[mt][nt][0], acc[mt][nt][1]);
            *(float2*)(out + (size_t)(r + 8) * 256 + n0) = make_float2(acc[mt][nt][2], acc[mt][nt][3]);
        }
}

extern "C" void kernel_launch(void* const* d_in, const int* in_sizes, int n_in,
                              void* d_out, int out_size) {
    (void)in_sizes; (void)n_in; (void)out_size;
    const float* in_pos = (const float*)d_in[0];
    const float* table  = (const float*)d_in[1];
    const float* ffn_A  = (const float*)d_in[2];
    const float* W0     = (const float*)d_in[3];
    const float* b0     = (const float*)d_in[4];
    const float* Ws     = (const float*)d_in[5];
    const float* bs     = (const float*)d_in[6];
    const float* Wh     = (const float*)d_in[7];
    const float* bh     = (const float*)d_in[8];
    float* out = (float*)d_out;

    cudaFuncSetAttribute(ffb_kernel, cudaFuncAttributeMaxDynamicSharedMemorySize, SMEM_TOTAL);

    prep_kernel<<<1536, 256>>>(Ws, Wh);
    ffb_kernel<<<262144 / TM, 512, SMEM_TOTAL>>>(in_pos, table, ffn_A, W0, b0, bs, bh, out);
}

// round 12
// speedup vs baseline: 1.5763x; 1.0582x over previous
#include <cuda_runtime.h>
#include <cuda_fp16.h>
#include <cstdint>
#include <cstddef>

// ---------------------------------------------------------------------------
// FFB encoder (round 11): K=64 phases (4 per GEMM), double-buffered W ring,
// fill-before-compute prefetch, barriers halved. 2m x 8n warp layout.
// 3-term compensated f16 mma.sync:  x@W = xh@Whi + xl@Whi + xh@Wlo
// ---------------------------------------------------------------------------

#define TM    64             // points per CTA
#define XH    264            // half stride of activation rows (528B = 33x16B: LDSM conflict-free)
#define WROW  272            // BYTES per W slab row: [64 hi | 64 lo] halfs + 16B pad (17x16B)
#define WBUFB 69632          // bytes per slab buffer (256 rows x 272B)

// ---- SMEM byte offsets ----
#define SM_XSH  0            // 33792
#define SM_XSL  33792        // 33792
#define SM_WBUF 67584        // 139264 (2 buffers x 69632 B)
#define SM_GSM  206848       // 3072:  [6][64][2] f32 grid feats
#define SM_ASM  209920       // 12288: [6][2][256] f32
#define SM_W0M  222208       // 4096:  scaled W0/b0
#define SM_PSM  226304       // 768:   [64][3]
#define SMEM_TOTAL 227072

// W planes: [l][part(hi=0,lo=1)][n][k] halfs
__device__ __align__(16) __half g_WsT[6 * 2 * 256 * 256];
__device__ __align__(16) __half g_WhT[6 * 2 * 256 * 256];

__device__ __forceinline__ unsigned smem_u32(const void* p) {
    unsigned a;
    asm("{ .reg .u64 t; cvta.to.shared.u64 t, %1; cvt.u32.u64 %0, t; }" : "=r"(a) : "l"(p));
    return a;
}

// range-reduced sin: full __sinf accuracy for |x| up to ~1e3
__device__ __forceinline__ float sinr(float x) {
    float k = rintf(x * 0.15915494309189535f);
    float r = fmaf(k, -6.2831855f, x);
    r = fmaf(k, 1.7484555e-7f, r);
    return __sinf(r);
}

__global__ void prep_kernel(const float* __restrict__ Ws, const float* __restrict__ Wh) {
    int idx = blockIdx.x * 256 + threadIdx.x;
    if (idx < 6 * 256 * 256) {
        int l = idx >> 16, rem = idx & 65535, n = rem >> 8, k = rem & 255;
        int src = (l << 16) + (k << 8) + n;             // transpose [k][n] -> [n][k]
        int dhi = ((l * 2 + 0) * 256 + n) * 256 + k;
        int dlo = ((l * 2 + 1) * 256 + n) * 256 + k;
        float ws = 5.0f * Ws[src];
        float wh = 10.0f * Wh[src];
        __half wsh = __float2half_rn(ws);
        __half whh = __float2half_rn(wh);
        g_WsT[dhi] = wsh; g_WsT[dlo] = __float2half_rn(ws - __half2float(wsh));
        g_WhT[dhi] = whh; g_WhT[dlo] = __float2half_rn(wh - __half2float(whh));
    }
}

__device__ __forceinline__ void mma16816(float* c, const unsigned* a, unsigned b0, unsigned b1) {
    asm volatile(
        "mma.sync.aligned.m16n8k16.row.col.f32.f16.f16.f32 "
        "{%0,%1,%2,%3}, {%4,%5,%6,%7}, {%8,%9}, {%0,%1,%2,%3};\n"
        : "+f"(c[0]), "+f"(c[1]), "+f"(c[2]), "+f"(c[3])
        : "r"(a[0]), "r"(a[1]), "r"(a[2]), "r"(a[3]), "r"(b0), "r"(b1));
}

#define LDSM_X4(r0, r1, r2, r3, addr) \
    asm volatile("ldmatrix.sync.aligned.m8n8.x4.shared.b16 {%0,%1,%2,%3}, [%4];" \
        : "=r"(r0), "=r"(r1), "=r"(r2), "=r"(r3) : "r"(addr))

__device__ __forceinline__ void cpasync16cg(unsigned dst, const void* src) {
    asm volatile("cp.async.cg.shared.global [%0], [%1], 16;\n" :: "r"(dst), "l"(src));
}
template <int NN> __device__ __forceinline__ void cpwait() {
    asm volatile("cp.async.wait_group %0;\n" :: "n"(NN));
}

// fill one K=64 phase slab (hi+lo per row) into buffer at smem byte addr bufb
// phase ph covers k in [ph*64, ph*64+64)
__device__ __forceinline__ void fill_slab(const __half* __restrict__ plane, int ph,
                                          unsigned bufb, int tid) {
    #pragma unroll
    for (int it = 0; it < 8; it++) {
        int c = tid + it * 512;              // 0..4095 16B-chunks
        int n = c >> 4, j = c & 15;
        int part = j >> 3, jj = j & 7;       // part: 0=hi, 1=lo; jj: 16B chunk in 128B
        const __half* src = plane + ((size_t)((part << 8) + n)) * 256 + ph * 64 + jj * 8;
        unsigned dst = bufb + (unsigned)(n * WROW + part * 128 + jj * 16);
        cpasync16cg(dst, src);
    }
    asm volatile("cp.async.commit_group;\n");
}

// C[64,256] += x @ W^T with 3-term compensation. 16 warps: 2m x 8n (m32 n32).
// Caller must have issued fill(plane, 0) into buffer 0 already.
// Double buffer, 4 phases of K=64; fill(p+1) issued BEFORE compute(p).
__device__ __forceinline__ void do_gemm(float (&c)[2][4][4],
                                        const __half* __restrict__ plane,
                                        unsigned sbase, unsigned aoff0, unsigned aoff1,
                                        unsigned brow, unsigned bcolB, int tid) {
    #pragma unroll 1
    for (int p = 0; p < 4; p++) {
        cpwait<0>();                         // phase-p slab landed
        __syncthreads();                     // visible to all; orders buffer reuse
        if (p < 3)
            fill_slab(plane, p + 1, sbase + SM_WBUF + (unsigned)(((p + 1) & 1) * WBUFB), tid);
        unsigned wb = sbase + SM_WBUF + (unsigned)((p & 1) * WBUFB);
        #pragma unroll
        for (int t = 0; t < 4; t++) {
            unsigned koff = (unsigned)((p * 64 + t * 16) * 2);
            unsigned tB = (unsigned)(t * 32);
            unsigned ah[2][4], al[2][4];
            LDSM_X4(ah[0][0], ah[0][1], ah[0][2], ah[0][3], sbase + SM_XSH + aoff0 + koff);
            LDSM_X4(ah[1][0], ah[1][1], ah[1][2], ah[1][3], sbase + SM_XSH + aoff1 + koff);
            LDSM_X4(al[0][0], al[0][1], al[0][2], al[0][3], sbase + SM_XSL + aoff0 + koff);
            LDSM_X4(al[1][0], al[1][1], al[1][2], al[1][3], sbase + SM_XSL + aoff1 + koff);
            unsigned b[4][2];
            // --- hi part of W ---
            #pragma unroll
            for (int ntp = 0; ntp < 2; ntp++) {
                unsigned r0, r1, r2, r3;
                LDSM_X4(r0, r1, r2, r3,
                        wb + (brow + (unsigned)(ntp * 16)) * WROW + bcolB + tB);
                b[2 * ntp][0] = r0; b[2 * ntp][1] = r1;
                b[2 * ntp + 1][0] = r2; b[2 * ntp + 1][1] = r3;
            }
            #pragma unroll
            for (int mt = 0; mt < 2; mt++)
                #pragma unroll
                for (int nt = 0; nt < 4; nt++) {
                    mma16816(c[mt][nt], ah[mt], b[nt][0], b[nt][1]);
                    mma16816(c[mt][nt], al[mt], b[nt][0], b[nt][1]);
                }
            // --- lo part of W ---
            #pragma unroll
            for (int ntp = 0; ntp < 2; ntp++) {
                unsigned r0, r1, r2, r3;
                LDSM_X4(r0, r1, r2, r3,
                        wb + (brow + (unsigned)(ntp * 16)) * WROW + 128 + bcolB + tB);
                b[2 * ntp][0] = r0; b[2 * ntp][1] = r1;
                b[2 * ntp + 1][0] = r2; b[2 * ntp + 1][1] = r3;
            }
            #pragma unroll
            for (int mt = 0; mt < 2; mt++)
                #pragma unroll
                for (int nt = 0; nt < 4; nt++)
                    mma16816(c[mt][nt], ah[mt], b[nt][0], b[nt][1]);
        }
    }
    __syncthreads();   // all compute done: caller may fill buf0 / write activations
}

__global__ void __launch_bounds__(512, 1) ffb_kernel(
    const float* __restrict__ in_pos, const float* __restrict__ table,
    const float* __restrict__ ffn_A, const float* __restrict__ W0,
    const float* __restrict__ b0v, const float* __restrict__ bsv,
    const float* __restrict__ bhv, float* __restrict__ out) {
    extern __shared__ char smem[];
    const unsigned sbase = smem_u32(smem);
    __half* xsh = (__half*)(smem + SM_XSH);
    __half* xsl = (__half*)(smem + SM_XSL);
    float* gsm = (float*)(smem + SM_GSM);
    float* Asm = (float*)(smem + SM_ASM);
    float* w0m = (float*)(smem + SM_W0M);
    float* psm = (float*)(smem + SM_PSM);

    const int tid = threadIdx.x;
    const int lane = tid & 31, wid = tid >> 5;
    const int g = lane >> 2, tg = lane & 3;
    const int wm = wid >> 3, wn = wid & 7;        // 2m x 8n warps
    const int rm = wm * 32, cn = wn * 32;
    const int row0 = blockIdx.x * TM;

    // ldmatrix address components
    const unsigned aoff0 = (unsigned)((rm + (lane & 15)) * XH + ((lane >> 4) << 3)) * 2;
    const unsigned aoff1 = aoff0 + (unsigned)(16 * XH) * 2;
    const unsigned brow = (unsigned)(cn + (lane & 7) + ((lane >> 4) << 3));   // row index
    const unsigned bcolB = (unsigned)(((lane >> 3) & 1) << 4);                // byte offset 0/16

    // ---- prologue staging ----
    for (int i = tid; i < TM * 3; i += 512) psm[i] = in_pos[row0 * 3 + i];
    for (int i = tid; i < 6 * 512; i += 512) {
        int l = i >> 9;
        Asm[i] = 6.283185307179586f * (5.0f * (float)(1 << l)) * ffn_A[i];
    }
    if (tid < 256) {
        w0m[tid] = 5.0f * W0[tid];
        w0m[256 + tid] = 5.0f * W0[256 + tid];
        w0m[512 + tid] = 5.0f * W0[512 + tid];
        w0m[768 + tid] = 5.0f * b0v[tid];
    }
    __syncthreads();

    // prefetch level-0 GEMM1 phase-0 — overlaps hash grid + layer 0
    fill_slab(g_WsT, 0, sbase + SM_WBUF, tid);

    // ---- multires hash grid (f32 math matches reference) ----
    if (tid < TM * 6) {
        int t = tid;
        int l = t >> 6;
        int p = t & 63;
        float res = 16.0f * (float)(1 << l);
        float px = (psm[p * 3 + 0] + 1.0f) * 0.5f * res;
        float py = (psm[p * 3 + 1] + 1.0f) * 0.5f * res;
        float pz = (psm[p * 3 + 2] + 1.0f) * 0.5f * res;
        float fx = floorf(px), fy = floorf(py), fz = floorf(pz);
        float frx = px - fx, fry = py - fy, frz = pz - fz;
        int ix = (int)fx, iy = (int)fy, iz = (int)fz;
        float g0 = 0.f, g1 = 0.f;
        const float* tb = table + (size_t)l * (524288 * 2);
        #pragma unroll
        for (int cc = 0; cc < 8; cc++) {
            int ox = (cc >> 2) & 1, oy = (cc >> 1) & 1, oz = cc & 1;
            unsigned h = ((unsigned)(ix + ox))
                       ^ ((unsigned)(iy + oy) * 2654435761u)
                       ^ ((unsigned)(iz + oz) * 805459861u);
            h &= 524287u;
            float2 f2 = *(const float2*)(tb + (size_t)h * 2);
            float w = (ox ? frx : 1.0f - frx) * (oy ? fry : 1.0f - fry) * (oz ? frz : 1.0f - frz);
            g0 = fmaf(w, f2.x, g0);
            g1 = fmaf(w, f2.y, g1);
        }
        gsm[t * 2] = g0; gsm[t * 2 + 1] = g1;
    }

    // ---- layer 0: x = sin(5*(pos @ W0 + b0)) -> hi/lo in smem ----
    for (int i = tid; i < TM * 256; i += 512) {
        int p = i >> 8, n = i & 255;
        float x = fmaf(psm[p * 3 + 2], w0m[512 + n],
                  fmaf(psm[p * 3 + 1], w0m[256 + n],
                  fmaf(psm[p * 3], w0m[n], w0m[768 + n])));
        float sv = sinr(x);
        __half h = __float2half_rn(sv);
        xsh[p * XH + n] = h;
        xsl[p * XH + n] = __float2half_rn(sv - __half2float(h));
    }
    // NOTE: no barrier here — do_gemm's phase-0 __syncthreads orders these
    // writes before any LDSM reads them.

    float acc[2][4][4];
    #pragma unroll
    for (int mt = 0; mt < 2; mt++)
        #pragma unroll
        for (int nt = 0; nt < 4; nt++)
            #pragma unroll
            for (int e = 0; e < 4; e++) acc[mt][nt][e] = 0.f;

    for (int lev = 0; lev < 6; lev++) {
        const __half* planeS = g_WsT + (size_t)lev * 131072;
        const __half* planeH = g_WhT + (size_t)lev * 131072;

        // ---- GEMM1: c = xs @ (5*Ws)^T + 5*bs ----
        float c[2][4][4];
        #pragma unroll
        for (int nt = 0; nt < 4; nt++) {
            float2 bv = *(const float2*)(bsv + lev * 256 + cn + nt * 8 + 2 * tg);
            float bx = 5.0f * bv.x, by = 5.0f * bv.y;
            #pragma unroll
            for (int mt = 0; mt < 2; mt++) {
                c[mt][nt][0] = bx; c[mt][nt][1] = by;
                c[mt][nt][2] = bx; c[mt][nt][3] = by;
            }
        }
        do_gemm(c, planeS, sbase, aoff0, aoff1, brow, bcolB, tid);

        // prefetch GEMM2 phase-0 — overlaps epilogue 1
        fill_slab(planeH, 0, sbase + SM_WBUF, tid);

        // ---- epilogue 1: x = sin(c) + sin(grid proj); write back hi/lo ----
        #pragma unroll
        for (int mt = 0; mt < 2; mt++) {
            int r0 = rm + mt * 16 + g;
            float2 gA = *(const float2*)(gsm + (lev * 64 + r0) * 2);
            float2 gB = *(const float2*)(gsm + (lev * 64 + r0 + 8) * 2);
            #pragma unroll
            for (int nt = 0; nt < 4; nt++) {
                int n0 = cn + nt * 8 + 2 * tg;
                float2 a0 = *(const float2*)(Asm + lev * 512 + n0);
                float2 a1 = *(const float2*)(Asm + lev * 512 + 256 + n0);
                float x0 = sinr(c[mt][nt][0]) + sinr(fmaf(gA.y, a1.x, gA.x * a0.x));
                float x1 = sinr(c[mt][nt][1]) + sinr(fmaf(gA.y, a1.y, gA.x * a0.y));
                float x2 = sinr(c[mt][nt][2]) + sinr(fmaf(gB.y, a1.x, gB.x * a0.x));
                float x3 = sinr(c[mt][nt][3]) + sinr(fmaf(gB.y, a1.y, gB.x * a0.y));
                __half h0 = __float2half_rn(x0), h1 = __float2half_rn(x1);
                __half h2 = __float2half_rn(x2), h3 = __float2half_rn(x3);
                *(__half2*)(xsh + r0 * XH + n0)       = __halves2half2(h0, h1);
                *(__half2*)(xsh + (r0 + 8) * XH + n0) = __halves2half2(h2, h3);
                *(__half2*)(xsl + r0 * XH + n0) =
                    __halves2half2(__float2half_rn(x0 - __half2float(h0)),
                                   __float2half_rn(x1 - __half2float(h1)));
                *(__half2*)(xsl + (r0 + 8) * XH + n0) =
                    __halves2half2(__float2half_rn(x2 - __half2float(h2)),
                                   __float2half_rn(x3 - __half2float(h3)));
            }
        }
        // no barrier: GEMM2 phase-0 __syncthreads orders these writes

        // ---- GEMM2: c2 = xs @ (10*Wh)^T + 10*bh; out += sin(c2) ----
        float c2[2][4][4];
        #pragma unroll
        for (int nt = 0; nt < 4; nt++) {
            float2 bv = *(const float2*)(bhv + lev * 256 + cn + nt * 8 + 2 * tg);
            float bx = 10.0f * bv.x, by = 10.0f * bv.y;
            #pragma unroll
            for (int mt = 0; mt < 2; mt++) {
                c2[mt][nt][0] = bx; c2[mt][nt][1] = by;
                c2[mt][nt][2] = bx; c2[mt][nt][3] = by;
            }
        }
        do_gemm(c2, planeH, sbase, aoff0, aoff1, brow, bcolB, tid);

        // prefetch next level's GEMM1 phase-0 — overlaps epilogue 2
        if (lev < 5)
            fill_slab(g_WsT + (size_t)(lev + 1) * 131072, 0, sbase + SM_WBUF, tid);

        // ---- epilogue 2: register-only accumulate ----
        #pragma unroll
        for (int mt = 0; mt < 2; mt++)
            #pragma unroll
            for (int nt = 0; nt < 4; nt++)
                #pragma unroll
                for (int e = 0; e < 4; e++)
                    acc[mt][nt][e] += sinr(c2[mt][nt][e]);
    }

    // ---- store out [N,256] f32 ----
    #pragma unroll
    for (int mt = 0; mt < 2; mt++)
        #pragma unroll
        for (int nt = 0; nt < 4; nt++) {
            int r = row0 + rm + mt * 16 + g;
            int n0 = cn + nt * 8 + 2 * tg;
            *(float2*)(out + (size_t)r * 256 + n0) = make_float2(acc[mt][nt][0], acc[mt][nt][1]);
            *(float2*)(out + (size_t)(r + 8) * 256 + n0) = make_float2(acc[mt][nt][2], acc[mt][nt][3]);
        }
}

extern "C" void kernel_launch(void* const* d_in, const int* in_sizes, int n_in,
                              void* d_out, int out_size) {
    (void)in_sizes; (void)n_in; (void)out_size;
    const float* in_pos = (const float*)d_in[0];
    const float* table  = (const float*)d_in[1];
    const float* ffn_A  = (const float*)d_in[2];
    const float* W0     = (const float*)d_in[3];
    const float* b0     = (const float*)d_in[4];
    const float* Ws     = (const float*)d_in[5];
    const float* bs     = (const float*)d_in[6];
    const float* Wh     = (const float*)d_in[7];
    const float* bh     = (const float*)d_in[8];
    float* out = (float*)d_out;

    cudaFuncSetAttribute(ffb_kernel, cudaFuncAttributeMaxDynamicSharedMemorySize, SMEM_TOTAL);

    prep_kernel<<<1536, 256>>>(Ws, Wh);
    ffb_kernel<<<262144 / TM, 512, SMEM_TOTAL>>>(in_pos, table, ffn_A, W0, b0, bs, bh, out);
}

// round 14
// speedup vs baseline: 2.0877x; 1.3244x over previous
#include <cuda_runtime.h>
#include <cuda_fp16.h>
#include <cstdint>
#include <cstddef>

// ---------------------------------------------------------------------------
// FFB encoder (round 13 = round 12 + uint4-stride fix): W staged in
// MMA-fragment order in gmem; B fragments loaded straight from L2 via LDG.128
// (no smem W, no cp.async, 2 __syncthreads per level). 3-term compensated
// f16 mma.sync:  x@W = xh@Whi + xl@Whi + xh@Wlo
// ---------------------------------------------------------------------------

#define TM    64             // points per CTA
#define XH    264            // half stride of activation rows (528B = 33x16B: LDSM conflict-free)

// ---- SMEM byte offsets ----
#define SM_XSH  0            // 33792
#define SM_XSL  33792        // 33792
#define SM_GSM  67584        // 3072:  [6][64][2] f32 grid feats
#define SM_ASM  70656        // 12288: [6][2][256] f32
#define SM_W0M  82944        // 4096:  scaled W0/b0
#define SM_PSM  87040        // 768:   [64][3]
#define SMEM_TOTAL 87808

// Fragment-ordered W planes: per (level, part): 65536 halves laid out as
// [nb16 0..15][t 0..15][lane 0..31][8 halves]; part: 0 = hi, 1 = lo.
__device__ __align__(16) __half g_WsF[6 * 2 * 65536];
__device__ __align__(16) __half g_WhF[6 * 2 * 65536];

__device__ __forceinline__ unsigned smem_u32(const void* p) {
    unsigned a;
    asm("{ .reg .u64 t; cvta.to.shared.u64 t, %1; cvt.u32.u64 %0, t; }" : "=r"(a) : "l"(p));
    return a;
}

// range-reduced sin: full __sinf accuracy for |x| up to ~1e3
__device__ __forceinline__ float sinr(float x) {
    float k = rintf(x * 0.15915494309189535f);
    float r = fmaf(k, -6.2831855f, x);
    r = fmaf(k, 1.7484555e-7f, r);
    return __sinf(r);
}

// prep: transpose + scale + hi/lo split + MMA-fragment-order scatter.
// Fragment contract (matches the passing LDSM path): lane = g*4+tg holds
//   slot 0,1 = W[nb16*16+g   ][16t+2tg+{0,1}]   (b0, lower n8)
//   slot 2,3 = W[nb16*16+g   ][16t+8+2tg+{0,1}] (b1, lower n8)
//   slot 4,5 = W[nb16*16+8+g ][16t+2tg+{0,1}]   (b0, upper n8)
//   slot 6,7 = W[nb16*16+8+g ][16t+8+2tg+{0,1}] (b1, upper n8)
__global__ void prep_kernel(const float* __restrict__ Ws, const float* __restrict__ Wh) {
    int idx = blockIdx.x * 256 + threadIdx.x;
    if (idx < 6 * 256 * 256) {
        int l = idx >> 16, rem = idx & 65535, n = rem >> 8, k = rem & 255;
        int src = (l << 16) + (k << 8) + n;             // [k][n] -> value at (n,k)
        float ws = 5.0f * Ws[src];
        float wh = 10.0f * Wh[src];
        __half wsh = __float2half_rn(ws);
        __half whh = __float2half_rn(wh);
        __half wsl = __float2half_rn(ws - __half2float(wsh));
        __half whl = __float2half_rn(wh - __half2float(whh));
        int nb16 = n >> 4, g = n & 7, n8sub = (n >> 3) & 1;
        int t = k >> 4, kk = k & 15;
        int khi = kk >> 3, tg = (kk & 7) >> 1, kp = kk & 1;
        int lane = g * 4 + tg;
        int slot = n8sub * 4 + khi * 2 + kp;
        size_t dst = (size_t)l * 131072 + (size_t)(nb16 * 16 + t) * 256 + lane * 8 + slot;
        g_WsF[dst] = wsh; g_WsF[dst + 65536] = wsl;
        g_WhF[dst] = whh; g_WhF[dst + 65536] = whl;
    }
}

__device__ __forceinline__ void mma16816(float* c, const unsigned* a, unsigned b0, unsigned b1) {
    asm volatile(
        "mma.sync.aligned.m16n8k16.row.col.f32.f16.f16.f32 "
        "{%0,%1,%2,%3}, {%4,%5,%6,%7}, {%8,%9}, {%0,%1,%2,%3};\n"
        : "+f"(c[0]), "+f"(c[1]), "+f"(c[2]), "+f"(c[3])
        : "r"(a[0]), "r"(a[1]), "r"(a[2]), "r"(a[3]), "r"(b0), "r"(b1));
}

#define LDSM_X4(r0, r1, r2, r3, addr) \
    asm volatile("ldmatrix.sync.aligned.m8n8.x4.shared.b16 {%0,%1,%2,%3}, [%4];" \
        : "=r"(r0), "=r"(r1), "=r"(r2), "=r"(r3) : "r"(addr))

// C[64,256] += x @ W^T with 3-term compensation. 16 warps: 2m x 8n (m32 n32).
// B fragments stream from gmem/L2, register double-buffered one t-step ahead.
// uint4 strides: one t-step = 256 halves = 32 uint4; one nb16 block = 512 uint4.
__device__ __forceinline__ void do_gemm(float (&c)[2][4][4],
                                        const __half* __restrict__ wfrag,
                                        unsigned sbase, unsigned aoff0, unsigned aoff1,
                                        unsigned boff) {
    const uint4* __restrict__ ph = (const uint4*)(wfrag + boff);            // hi part
    const uint4* __restrict__ pl = (const uint4*)(wfrag + 65536 + boff);    // lo part
    uint4 vh[2][2], vl[2][2];
    vh[0][0] = ph[0];   vh[0][1] = ph[512];
    vl[0][0] = pl[0];   vl[0][1] = pl[512];
    #pragma unroll 2
    for (int t = 0; t < 16; t++) {
        const int cur = t & 1, nxt = cur ^ 1;
        if (t < 15) {
            vh[nxt][0] = ph[(t + 1) * 32];
            vh[nxt][1] = ph[512 + (t + 1) * 32];
            vl[nxt][0] = pl[(t + 1) * 32];
            vl[nxt][1] = pl[512 + (t + 1) * 32];
        }
        unsigned koff = (unsigned)(t * 32);
        unsigned ah[2][4], al[2][4];
        LDSM_X4(ah[0][0], ah[0][1], ah[0][2], ah[0][3], sbase + SM_XSH + aoff0 + koff);
        LDSM_X4(ah[1][0], ah[1][1], ah[1][2], ah[1][3], sbase + SM_XSH + aoff1 + koff);
        LDSM_X4(al[0][0], al[0][1], al[0][2], al[0][3], sbase + SM_XSL + aoff0 + koff);
        LDSM_X4(al[1][0], al[1][1], al[1][2], al[1][3], sbase + SM_XSL + aoff1 + koff);
        unsigned b[4][2];
        // --- hi part of W ---
        b[0][0] = vh[cur][0].x; b[0][1] = vh[cur][0].y;
        b[1][0] = vh[cur][0].z; b[1][1] = vh[cur][0].w;
        b[2][0] = vh[cur][1].x; b[2][1] = vh[cur][1].y;
        b[3][0] = vh[cur][1].z; b[3][1] = vh[cur][1].w;
        #pragma unroll
        for (int mt = 0; mt < 2; mt++)
            #pragma unroll
            for (int nt = 0; nt < 4; nt++) {
                mma16816(c[mt][nt], ah[mt], b[nt][0], b[nt][1]);
                mma16816(c[mt][nt], al[mt], b[nt][0], b[nt][1]);
            }
        // --- lo part of W ---
        b[0][0] = vl[cur][0].x; b[0][1] = vl[cur][0].y;
        b[1][0] = vl[cur][0].z; b[1][1] = vl[cur][0].w;
        b[2][0] = vl[cur][1].x; b[2][1] = vl[cur][1].y;
        b[3][0] = vl[cur][1].z; b[3][1] = vl[cur][1].w;
        #pragma unroll
        for (int mt = 0; mt < 2; mt++)
            #pragma unroll
            for (int nt = 0; nt < 4; nt++)
                mma16816(c[mt][nt], ah[mt], b[nt][0], b[nt][1]);
    }
}

__global__ void __launch_bounds__(512, 1) ffb_kernel(
    const float* __restrict__ in_pos, const float* __restrict__ table,
    const float* __restrict__ ffn_A, const float* __restrict__ W0,
    const float* __restrict__ b0v, const float* __restrict__ bsv,
    const float* __restrict__ bhv, float* __restrict__ out) {
    extern __shared__ char smem[];
    const unsigned sbase = smem_u32(smem);
    __half* xsh = (__half*)(smem + SM_XSH);
    __half* xsl = (__half*)(smem + SM_XSL);
    float* gsm = (float*)(smem + SM_GSM);
    float* Asm = (float*)(smem + SM_ASM);
    float* w0m = (float*)(smem + SM_W0M);
    float* psm = (float*)(smem + SM_PSM);

    const int tid = threadIdx.x;
    const int lane = tid & 31, wid = tid >> 5;
    const int g = lane >> 2, tg = lane & 3;
    const int wm = wid >> 3, wn = wid & 7;        // 2m x 8n warps
    const int rm = wm * 32, cn = wn * 32;
    const int row0 = blockIdx.x * TM;

    // ldmatrix address components (byte offsets)
    const unsigned aoff0 = (unsigned)((rm + (lane & 15)) * XH + ((lane >> 4) << 3)) * 2;
    const unsigned aoff1 = aoff0 + (unsigned)(16 * XH) * 2;
    // B fragment offset in halves: nb16 = wn*2 -> wn*2*4096, + lane*8
    const unsigned boff = (unsigned)(wn * 8192 + lane * 8);

    // ---- prologue staging ----
    for (int i = tid; i < TM * 3; i += 512) psm[i] = in_pos[row0 * 3 + i];
    for (int i = tid; i < 6 * 512; i += 512) {
        int l = i >> 9;
        Asm[i] = 6.283185307179586f * (5.0f * (float)(1 << l)) * ffn_A[i];
    }
    if (tid < 256) {
        w0m[tid] = 5.0f * W0[tid];
        w0m[256 + tid] = 5.0f * W0[256 + tid];
        w0m[512 + tid] = 5.0f * W0[512 + tid];
        w0m[768 + tid] = 5.0f * b0v[tid];
    }
    __syncthreads();

    // ---- multires hash grid (f32 math matches reference) ----
    if (tid < TM * 6) {
        int t = tid;
        int l = t >> 6;
        int p = t & 63;
        float res = 16.0f * (float)(1 << l);
        float px = (psm[p * 3 + 0] + 1.0f) * 0.5f * res;
        float py = (psm[p * 3 + 1] + 1.0f) * 0.5f * res;
        float pz = (psm[p * 3 + 2] + 1.0f) * 0.5f * res;
        float fx = floorf(px), fy = floorf(py), fz = floorf(pz);
        float frx = px - fx, fry = py - fy, frz = pz - fz;
        int ix = (int)fx, iy = (int)fy, iz = (int)fz;
        float g0 = 0.f, g1 = 0.f;
        const float* tb = table + (size_t)l * (524288 * 2);
        #pragma unroll
        for (int cc = 0; cc < 8; cc++) {
            int ox = (cc >> 2) & 1, oy = (cc >> 1) & 1, oz = cc & 1;
            unsigned h = ((unsigned)(ix + ox))
                       ^ ((unsigned)(iy + oy) * 2654435761u)
                       ^ ((unsigned)(iz + oz) * 805459861u);
            h &= 524287u;
            float2 f2 = *(const float2*)(tb + (size_t)h * 2);
            float w = (ox ? frx : 1.0f - frx) * (oy ? fry : 1.0f - fry) * (oz ? frz : 1.0f - frz);
            g0 = fmaf(w, f2.x, g0);
            g1 = fmaf(w, f2.y, g1);
        }
        gsm[t * 2] = g0; gsm[t * 2 + 1] = g1;
    }

    // ---- layer 0: x = sin(5*(pos @ W0 + b0)) -> hi/lo in smem ----
    for (int i = tid; i < TM * 256; i += 512) {
        int p = i >> 8, n = i & 255;
        float x = fmaf(psm[p * 3 + 2], w0m[512 + n],
                  fmaf(psm[p * 3 + 1], w0m[256 + n],
                  fmaf(psm[p * 3], w0m[n], w0m[768 + n])));
        float sv = sinr(x);
        __half h = __float2half_rn(sv);
        xsh[p * XH + n] = h;
        xsl[p * XH + n] = __float2half_rn(sv - __half2float(h));
    }
    __syncthreads();   // xs + gsm visible before GEMM1 reads

    float acc[2][4][4];
    #pragma unroll
    for (int mt = 0; mt < 2; mt++)
        #pragma unroll
        for (int nt = 0; nt < 4; nt++)
            #pragma unroll
            for (int e = 0; e < 4; e++) acc[mt][nt][e] = 0.f;

    for (int lev = 0; lev < 6; lev++) {
        // ---- GEMM1: c = xs @ (5*Ws)^T + 5*bs ----
        float c[2][4][4];
        #pragma unroll
        for (int nt = 0; nt < 4; nt++) {
            float2 bv = *(const float2*)(bsv + lev * 256 + cn + nt * 8 + 2 * tg);
            float bx = 5.0f * bv.x, by = 5.0f * bv.y;
            #pragma unroll
            for (int mt = 0; mt < 2; mt++) {
                c[mt][nt][0] = bx; c[mt][nt][1] = by;
                c[mt][nt][2] = bx; c[mt][nt][3] = by;
            }
        }
        do_gemm(c, g_WsF + (size_t)lev * 131072, sbase, aoff0, aoff1, boff);
        __syncthreads();   // all xs reads (GEMM2(lev-1) + GEMM1(lev)) done: WAR safe

        // ---- epilogue 1: x = sin(c) + sin(grid proj); write back hi/lo ----
        #pragma unroll
        for (int mt = 0; mt < 2; mt++) {
            int r0 = rm + mt * 16 + g;
            float2 gA = *(const float2*)(gsm + (lev * 64 + r0) * 2);
            float2 gB = *(const float2*)(gsm + (lev * 64 + r0 + 8) * 2);
            #pragma unroll
            for (int nt = 0; nt < 4; nt++) {
                int n0 = cn + nt * 8 + 2 * tg;
                float2 a0 = *(const float2*)(Asm + lev * 512 + n0);
                float2 a1 = *(const float2*)(Asm + lev * 512 + 256 + n0);
                float x0 = sinr(c[mt][nt][0]) + sinr(fmaf(gA.y, a1.x, gA.x * a0.x));
                float x1 = sinr(c[mt][nt][1]) + sinr(fmaf(gA.y, a1.y, gA.x * a0.y));
                float x2 = sinr(c[mt][nt][2]) + sinr(fmaf(gB.y, a1.x, gB.x * a0.x));
                float x3 = sinr(c[mt][nt][3]) + sinr(fmaf(gB.y, a1.y, gB.x * a0.y));
                __half h0 = __float2half_rn(x0), h1 = __float2half_rn(x1);
                __half h2 = __float2half_rn(x2), h3 = __float2half_rn(x3);
                *(__half2*)(xsh + r0 * XH + n0)       = __halves2half2(h0, h1);
                *(__half2*)(xsh + (r0 + 8) * XH + n0) = __halves2half2(h2, h3);
                *(__half2*)(xsl + r0 * XH + n0) =
                    __halves2half2(__float2half_rn(x0 - __half2float(h0)),
                                   __float2half_rn(x1 - __half2float(h1)));
                *(__half2*)(xsl + (r0 + 8) * XH + n0) =
                    __halves2half2(__float2half_rn(x2 - __half2float(h2)),
                                   __float2half_rn(x3 - __half2float(h3)));
            }
        }
        __syncthreads();   // xs writes visible before GEMM2 reads

        // ---- GEMM2: c2 = xs @ (10*Wh)^T + 10*bh; out += sin(c2) ----
        float c2[2][4][4];
        #pragma unroll
        for (int nt = 0; nt < 4; nt++) {
            float2 bv = *(const float2*)(bhv + lev * 256 + cn + nt * 8 + 2 * tg);
            float bx = 10.0f * bv.x, by = 10.0f * bv.y;
            #pragma unroll
            for (int mt = 0; mt < 2; mt++) {
                c2[mt][nt][0] = bx; c2[mt][nt][1] = by;
                c2[mt][nt][2] = bx; c2[mt][nt][3] = by;
            }
        }
        do_gemm(c2, g_WhF + (size_t)lev * 131072, sbase, aoff0, aoff1, boff);

        // ---- epilogue 2: register-only accumulate (overlaps next GEMM1 across warps) ----
        #pragma unroll
        for (int mt = 0; mt < 2; mt++)
            #pragma unroll
            for (int nt = 0; nt < 4; nt++)
                #pragma unroll
                for (int e = 0; e < 4; e++)
                    acc[mt][nt][e] += sinr(c2[mt][nt][e]);
        // no barrier: next GEMM1 re-reads the SAME xs (x only changes in epilogue 1)
    }

    // ---- store out [N,256] f32 ----
    #pragma unroll
    for (int mt = 0; mt < 2; mt++)
        #pragma unroll
        for (int nt = 0; nt < 4; nt++) {
            int r = row0 + rm + mt * 16 + g;
            int n0 = cn + nt * 8 + 2 * tg;
            *(float2*)(out + (size_t)r * 256 + n0) = make_float2(acc[mt][nt][0], acc[mt][nt][1]);
            *(float2*)(out + (size_t)(r + 8) * 256 + n0) = make_float2(acc[mt][nt][2], acc[mt][nt][3]);
        }
}

extern "C" void kernel_launch(void* const* d_in, const int* in_sizes, int n_in,
                              void* d_out, int out_size) {
    (void)in_sizes; (void)n_in; (void)out_size;
    const float* in_pos = (const float*)d_in[0];
    const float* table  = (const float*)d_in[1];
    const float* ffn_A  = (const float*)d_in[2];
    const float* W0     = (const float*)d_in[3];
    const float* b0     = (const float*)d_in[4];
    const float* Ws     = (const float*)d_in[5];
    const float* bs     = (const float*)d_in[6];
    const float* Wh     = (const float*)d_in[7];
    const float* bh     = (const float*)d_in[8];
    float* out = (float*)d_out;

    cudaFuncSetAttribute(ffb_kernel, cudaFuncAttributeMaxDynamicSharedMemorySize, SMEM_TOTAL);

    prep_kernel<<<1536, 256>>>(Ws, Wh);
    ffb_kernel<<<262144 / TM, 512, SMEM_TOTAL>>>(in_pos, table, ffn_A, W0, b0, bs, bh, out);
}